// round 1
// baseline (speedup 1.0000x reference)
#include <cuda_runtime.h>
#include <cuda_bf16.h>
#include <math.h>

// Problem constants
#define BATCH 2
#define SEQ   2048
#define EMB   1024
#define NHEAD 16
#define HDIM  64
#define MROWS (BATCH * SEQ)      // 4096
#define ATTN_SCALE 0.125f        // 1/sqrt(64)

// ---------------------------------------------------------------------------
// Scratch (allocation-free rule: __device__ globals)
// ---------------------------------------------------------------------------
__device__ float g_Q[MROWS * EMB];
__device__ float g_K[MROWS * EMB];
__device__ float g_V[MROWS * EMB];
__device__ float g_A[MROWS * EMB];

// ---------------------------------------------------------------------------
// GEMM: C[M,N] = A[M,K] @ B[N,K]^T + bias[N]
// 128x128 tile, BK=16, 256 threads, 8x8 per thread. All dims divide evenly.
// ---------------------------------------------------------------------------
#define GBM 128
#define GBN 128
#define GBK 16

__global__ void __launch_bounds__(256)
gemm_nt_bias(const float* __restrict__ A, const float* __restrict__ Bw,
             const float* __restrict__ bias, float* __restrict__ C,
             int Mdim, int Ndim, int Kdim)
{
    __shared__ float As[GBK][GBM];
    __shared__ float Bs[GBK][GBN];

    const int tid    = threadIdx.x;
    const int rowBlk = blockIdx.y * GBM;
    const int colBlk = blockIdx.x * GBN;
    const int tr = tid / 16;   // 0..15
    const int tc = tid % 16;   // 0..15

    float acc[8][8];
#pragma unroll
    for (int i = 0; i < 8; i++)
#pragma unroll
        for (int j = 0; j < 8; j++) acc[i][j] = 0.f;

    for (int k0 = 0; k0 < Kdim; k0 += GBK) {
        // load 128x16 A tile and 128x16 B tile (each 512 float4s, 2 per thread)
#pragma unroll
        for (int it = 0; it < 2; it++) {
            int f  = tid + it * 256;     // 0..511
            int r  = f >> 2;             // 0..127
            int c4 = f & 3;              // 0..3
            float4 va = *(const float4*)&A[(size_t)(rowBlk + r) * Kdim + k0 + c4 * 4];
            As[c4 * 4 + 0][r] = va.x;
            As[c4 * 4 + 1][r] = va.y;
            As[c4 * 4 + 2][r] = va.z;
            As[c4 * 4 + 3][r] = va.w;
            float4 vb = *(const float4*)&Bw[(size_t)(colBlk + r) * Kdim + k0 + c4 * 4];
            Bs[c4 * 4 + 0][r] = vb.x;
            Bs[c4 * 4 + 1][r] = vb.y;
            Bs[c4 * 4 + 2][r] = vb.z;
            Bs[c4 * 4 + 3][r] = vb.w;
        }
        __syncthreads();

#pragma unroll
        for (int kk = 0; kk < GBK; kk++) {
            float a[8], b[8];
            float4 a0 = *(const float4*)&As[kk][tr * 8];
            float4 a1 = *(const float4*)&As[kk][tr * 8 + 4];
            float4 b0 = *(const float4*)&Bs[kk][tc * 8];
            float4 b1 = *(const float4*)&Bs[kk][tc * 8 + 4];
            a[0]=a0.x; a[1]=a0.y; a[2]=a0.z; a[3]=a0.w;
            a[4]=a1.x; a[5]=a1.y; a[6]=a1.z; a[7]=a1.w;
            b[0]=b0.x; b[1]=b0.y; b[2]=b0.z; b[3]=b0.w;
            b[4]=b1.x; b[5]=b1.y; b[6]=b1.z; b[7]=b1.w;
#pragma unroll
            for (int i = 0; i < 8; i++)
#pragma unroll
                for (int j = 0; j < 8; j++)
                    acc[i][j] += a[i] * b[j];
        }
        __syncthreads();
    }

    // store with bias, vectorized
#pragma unroll
    for (int i = 0; i < 8; i++) {
        int row = rowBlk + tr * 8 + i;
#pragma unroll
        for (int j4 = 0; j4 < 2; j4++) {
            int col = colBlk + tc * 8 + j4 * 4;
            float4 st;
            st.x = acc[i][j4 * 4 + 0] + bias[col + 0];
            st.y = acc[i][j4 * 4 + 1] + bias[col + 1];
            st.z = acc[i][j4 * 4 + 2] + bias[col + 2];
            st.w = acc[i][j4 * 4 + 3] + bias[col + 3];
            *(float4*)&C[(size_t)row * Ndim + col] = st;
        }
    }
}

// ---------------------------------------------------------------------------
// Causal flash attention.
// Grid: (SEQ/128, BATCH*NHEAD). Block: 128 threads, 1 query per thread.
// Q,K,V layout: [B*S, EMB] with head h at column offset h*HDIM.
// ---------------------------------------------------------------------------
__global__ void __launch_bounds__(128)
attn_kernel(const float* __restrict__ Q, const float* __restrict__ K,
            const float* __restrict__ V, float* __restrict__ O)
{
    __shared__ float Ks[64][64];
    __shared__ float Vs[64][64];

    const int bh = blockIdx.y;
    const int b  = bh >> 4;
    const int h  = bh & 15;
    const int qi = blockIdx.x * 128 + threadIdx.x;   // this thread's query row

    const float* qptr = Q + ((size_t)(b * SEQ + qi)) * EMB + h * HDIM;
    float4 q4[16];
#pragma unroll
    for (int i = 0; i < 16; i++) q4[i] = ((const float4*)qptr)[i];

    float4 o4[16];
#pragma unroll
    for (int i = 0; i < 16; i++) o4[i] = make_float4(0.f, 0.f, 0.f, 0.f);

    float m = -1e30f, l = 0.f;

    const float* Kbase = K + ((size_t)b * SEQ) * EMB + h * HDIM;
    const float* Vbase = V + ((size_t)b * SEQ) * EMB + h * HDIM;

    const int nTiles = blockIdx.x * 2 + 2;   // covers keys up to block's last query

    for (int t = 0; t < nTiles; t++) {
        const int base = t * 64;
        __syncthreads();   // previous tile fully consumed
        // cooperative load of K/V 64x64 tiles (1024 float4 each)
        for (int f = threadIdx.x; f < 64 * 16; f += 128) {
            int r = f >> 4;
            int c = f & 15;
            ((float4*)Ks[r])[c] = ((const float4*)(Kbase + (size_t)(base + r) * EMB))[c];
            ((float4*)Vs[r])[c] = ((const float4*)(Vbase + (size_t)(base + r) * EMB))[c];
        }
        __syncthreads();

        // 4 sub-chunks of 16 keys; scores live in registers
#pragma unroll 1
        for (int sc = 0; sc < 4; sc++) {
            const int j0 = base + sc * 16;
            if (j0 > qi) break;   // fully masked for this thread

            float s[16];
#pragma unroll
            for (int j = 0; j < 16; j++) {
                const float4* kr = (const float4*)Ks[sc * 16 + j];
                float acc0 = 0.f, acc1 = 0.f, acc2 = 0.f, acc3 = 0.f;
#pragma unroll
                for (int d = 0; d < 16; d += 4) {
                    float4 k0v = kr[d + 0];
                    float4 k1v = kr[d + 1];
                    float4 k2v = kr[d + 2];
                    float4 k3v = kr[d + 3];
                    acc0 += q4[d+0].x*k0v.x + q4[d+0].y*k0v.y + q4[d+0].z*k0v.z + q4[d+0].w*k0v.w;
                    acc1 += q4[d+1].x*k1v.x + q4[d+1].y*k1v.y + q4[d+1].z*k1v.z + q4[d+1].w*k1v.w;
                    acc2 += q4[d+2].x*k2v.x + q4[d+2].y*k2v.y + q4[d+2].z*k2v.z + q4[d+2].w*k2v.w;
                    acc3 += q4[d+3].x*k3v.x + q4[d+3].y*k3v.y + q4[d+3].z*k3v.z + q4[d+3].w*k3v.w;
                }
                float sv = (acc0 + acc1 + acc2 + acc3) * ATTN_SCALE;
                s[j] = (j0 + j > qi) ? -1e30f : sv;
            }

            float cmax = s[0];
#pragma unroll
            for (int j = 1; j < 16; j++) cmax = fmaxf(cmax, s[j]);
            float mn   = fmaxf(m, cmax);
            float corr = __expf(m - mn);
            l *= corr;
#pragma unroll
            for (int i = 0; i < 16; i++) {
                o4[i].x *= corr; o4[i].y *= corr; o4[i].z *= corr; o4[i].w *= corr;
            }
            m = mn;

#pragma unroll
            for (int j = 0; j < 16; j++) {
                float p = __expf(s[j] - mn);
                l += p;
                const float4* vr = (const float4*)Vs[sc * 16 + j];
#pragma unroll
                for (int d = 0; d < 16; d++) {
                    float4 vv = vr[d];
                    o4[d].x += p * vv.x;
                    o4[d].y += p * vv.y;
                    o4[d].z += p * vv.z;
                    o4[d].w += p * vv.w;
                }
            }
        }
    }

    const float inv = 1.f / l;
    float* optr = O + ((size_t)(b * SEQ + qi)) * EMB + h * HDIM;
#pragma unroll
    for (int i = 0; i < 16; i++) {
        float4 st;
        st.x = o4[i].x * inv; st.y = o4[i].y * inv;
        st.z = o4[i].z * inv; st.w = o4[i].w * inv;
        ((float4*)optr)[i] = st;
    }
}

// ---------------------------------------------------------------------------
// Launch
// ---------------------------------------------------------------------------
extern "C" void kernel_launch(void* const* d_in, const int* in_sizes, int n_in,
                              void* d_out, int out_size)
{
    const float* xq = (const float*)d_in[0];
    const float* xk = (const float*)d_in[1];
    const float* xv = (const float*)d_in[2];
    // d_in[3] = mask (deterministic causal tril) — exploited structurally
    const float* Wq = (const float*)d_in[4];
    const float* bq = (const float*)d_in[5];
    const float* Wk = (const float*)d_in[6];
    const float* bk = (const float*)d_in[7];
    const float* Wv = (const float*)d_in[8];
    const float* bv = (const float*)d_in[9];
    const float* Wo = (const float*)d_in[10];
    const float* bo = (const float*)d_in[11];
    float* out = (float*)d_out;

    float *pQ, *pK, *pV, *pA;
    cudaGetSymbolAddress((void**)&pQ, g_Q);
    cudaGetSymbolAddress((void**)&pK, g_K);
    cudaGetSymbolAddress((void**)&pV, g_V);
    cudaGetSymbolAddress((void**)&pA, g_A);

    dim3 ggrid(EMB / GBN, MROWS / GBM);   // (8, 32)
    gemm_nt_bias<<<ggrid, 256>>>(xq, Wq, bq, pQ, MROWS, EMB, EMB);
    gemm_nt_bias<<<ggrid, 256>>>(xk, Wk, bk, pK, MROWS, EMB, EMB);
    gemm_nt_bias<<<ggrid, 256>>>(xv, Wv, bv, pV, MROWS, EMB, EMB);

    dim3 agrid(SEQ / 128, BATCH * NHEAD); // (16, 32)
    attn_kernel<<<agrid, 128>>>(pQ, pK, pV, pA);

    gemm_nt_bias<<<ggrid, 256>>>(pA, Wo, bo, out, MROWS, EMB, EMB);
}

// round 3
// speedup vs baseline: 1.3356x; 1.3356x over previous
#include <cuda_runtime.h>
#include <cuda_bf16.h>
#include <stdint.h>
#include <math.h>

// Problem constants
#define BATCH 2
#define SEQ   2048
#define EMB   1024
#define NHEAD 16
#define HDIM  64
#define MROWS (BATCH * SEQ)      // 4096
#define ATTN_SCALE 0.125f        // 1/sqrt(64)

// ---------------------------------------------------------------------------
// Scratch (allocation-free rule: __device__ globals)
// ---------------------------------------------------------------------------
__device__ float g_Q[MROWS * EMB];
__device__ float g_K[MROWS * EMB];
__device__ float g_V[MROWS * EMB];
__device__ float g_A[MROWS * EMB];

// ---------------------------------------------------------------------------
// tf32 helpers
// ---------------------------------------------------------------------------
__device__ __forceinline__ uint32_t f2tf32(float x) {
    uint32_t u;
    asm("cvt.rna.tf32.f32 %0, %1;" : "=r"(u) : "f"(x));
    return u;
}

__device__ __forceinline__ void mma8(float* c, const uint32_t* a, const uint32_t* b) {
    asm volatile(
        "mma.sync.aligned.m16n8k8.row.col.f32.tf32.tf32.f32 "
        "{%0,%1,%2,%3}, {%4,%5,%6,%7}, {%8,%9}, {%0,%1,%2,%3};"
        : "+f"(c[0]), "+f"(c[1]), "+f"(c[2]), "+f"(c[3])
        : "r"(a[0]), "r"(a[1]), "r"(a[2]), "r"(a[3]), "r"(b[0]), "r"(b[1]));
}

// ---------------------------------------------------------------------------
// GEMM: C[4096,1024] = A[4096,1024] @ W[1024,1024]^T + bias
// CTA tile 128x128, K-step 32. 256 threads = 8 warps, warp tile 64x32.
// SMEM holds tiles pre-permuted into mma fragment order:
//   A frag layout (m16n8k8.tf32): a0=(r,c) a1=(r+8,c) a2=(r,c+4) a3=(r+8,c+4)
//     with r = lane>>2 (+8), c = lane&3 (+4)
//   B frag: b0=(k=lane&3, n=lane>>2), b1=(k+4, n)
// ---------------------------------------------------------------------------
__global__ void __launch_bounds__(256)
gemm_tf32(const float* __restrict__ A, const float* __restrict__ Bw,
          const float* __restrict__ bias, float* __restrict__ C)
{
    // [m16_tile][k8_tile][lane][frag]
    __shared__ uint32_t Asb[8][4][32][4];    // 16 KB
    // [n8_tile][k8_tile][lane][frag]
    __shared__ uint32_t Bsb[16][4][32][2];   // 16 KB

    const int tid  = threadIdx.x;
    const int lane = tid & 31;
    const int warp = tid >> 5;
    const int wm   = warp & 1;    // 0..1 (m offset wm*64)
    const int wn   = warp >> 1;   // 0..3 (n offset wn*32)
    const int rowBlk = blockIdx.y * 128;
    const int colBlk = blockIdx.x * 128;

    float acc[4][4][4];
#pragma unroll
    for (int mi = 0; mi < 4; mi++)
#pragma unroll
        for (int ni = 0; ni < 4; ni++)
#pragma unroll
            for (int q = 0; q < 4; q++) acc[mi][ni][q] = 0.f;

    for (int k0 = 0; k0 < EMB; k0 += 32) {
        // ---- prefetch global (overlaps previous stage's mma work) ----
        float4 va[4], vb[4];
#pragma unroll
        for (int it = 0; it < 4; it++) {
            int f  = tid + it * 256;     // 0..1023
            int m  = f >> 3;             // 0..127
            int k4 = f & 7;              // 0..7 (float4 index within 32-wide k)
            va[it] = *(const float4*)&A [(size_t)(rowBlk + m) * EMB + k0 + k4 * 4];
            vb[it] = *(const float4*)&Bw[(size_t)(colBlk + m) * EMB + k0 + k4 * 4];
        }
        __syncthreads();   // previous stage fully consumed

        // ---- store into fragment-permuted SMEM (tf32-converted) ----
#pragma unroll
        for (int it = 0; it < 4; it++) {
            int f  = tid + it * 256;
            int m  = f >> 3;
            int k4 = f & 7;
            int kt = k4 >> 1;            // k8 tile 0..3
            int hi = k4 & 1;             // upper half of k8 (c>=4)?
            uint32_t ua[4] = { f2tf32(va[it].x), f2tf32(va[it].y),
                               f2tf32(va[it].z), f2tf32(va[it].w) };
            uint32_t ub[4] = { f2tf32(vb[it].x), f2tf32(vb[it].y),
                               f2tf32(vb[it].z), f2tf32(vb[it].w) };
            int mt  = m >> 4;            // m16 tile
            int rhi = (m >> 3) & 1;      // row >= 8 within m16?
            int ga  = m & 7;             // lane group (row low bits)
            int nt  = m >> 3;            // n8 tile (for B, f decodes n the same way)
            int gb  = m & 7;             // n within n8 tile
#pragma unroll
            for (int j = 0; j < 4; j++) {
                // element col c = k4*4+j, c&3 == j
                Asb[mt][kt][ga * 4 + j][rhi + 2 * hi] = ua[j];
                Bsb[nt][kt][gb * 4 + j][hi]           = ub[j];
            }
        }
        __syncthreads();

        // ---- mma mainloop over the 4 k8-steps ----
#pragma unroll
        for (int kt = 0; kt < 4; kt++) {
            uint32_t af[4][4];
            uint32_t bf[4][2];
#pragma unroll
            for (int mi = 0; mi < 4; mi++) {
                uint4 t = *(const uint4*)&Asb[wm * 4 + mi][kt][lane][0];
                af[mi][0] = t.x; af[mi][1] = t.y; af[mi][2] = t.z; af[mi][3] = t.w;
            }
#pragma unroll
            for (int ni = 0; ni < 4; ni++) {
                uint2 t = *(const uint2*)&Bsb[wn * 4 + ni][kt][lane][0];
                bf[ni][0] = t.x; bf[ni][1] = t.y;
            }
#pragma unroll
            for (int mi = 0; mi < 4; mi++)
#pragma unroll
                for (int ni = 0; ni < 4; ni++)
                    mma8(acc[mi][ni], af[mi], bf[ni]);
        }
    }

    // ---- epilogue: bias + store ----
    const int g  = lane >> 2;       // row within m16 (also row group for C)
    const int tg = lane & 3;
#pragma unroll
    for (int mi = 0; mi < 4; mi++) {
        int r0 = rowBlk + wm * 64 + mi * 16 + g;
#pragma unroll
        for (int ni = 0; ni < 4; ni++) {
            int c0 = colBlk + wn * 32 + ni * 8 + tg * 2;
            float2 bb = *(const float2*)&bias[c0];
            float2 s0 = make_float2(acc[mi][ni][0] + bb.x, acc[mi][ni][1] + bb.y);
            float2 s1 = make_float2(acc[mi][ni][2] + bb.x, acc[mi][ni][3] + bb.y);
            *(float2*)&C[(size_t)r0 * EMB + c0]       = s0;
            *(float2*)&C[(size_t)(r0 + 8) * EMB + c0] = s1;
        }
    }
}

// ---------------------------------------------------------------------------
// Causal flash attention (fp32, 1 query/thread).
// ---------------------------------------------------------------------------
__global__ void __launch_bounds__(128)
attn_kernel(const float* __restrict__ Q, const float* __restrict__ K,
            const float* __restrict__ V, float* __restrict__ O)
{
    __shared__ float Ks[64][64];
    __shared__ float Vs[64][64];

    const int bh = blockIdx.y;
    const int b  = bh >> 4;
    const int h  = bh & 15;
    const int qi = blockIdx.x * 128 + threadIdx.x;

    const float* qptr = Q + ((size_t)(b * SEQ + qi)) * EMB + h * HDIM;
    float4 q4[16];
#pragma unroll
    for (int i = 0; i < 16; i++) q4[i] = ((const float4*)qptr)[i];

    float4 o4[16];
#pragma unroll
    for (int i = 0; i < 16; i++) o4[i] = make_float4(0.f, 0.f, 0.f, 0.f);

    float m = -1e30f, l = 0.f;

    const float* Kbase = K + ((size_t)b * SEQ) * EMB + h * HDIM;
    const float* Vbase = V + ((size_t)b * SEQ) * EMB + h * HDIM;

    const int nTiles = blockIdx.x * 2 + 2;

    for (int t = 0; t < nTiles; t++) {
        const int base = t * 64;
        __syncthreads();
        for (int f = threadIdx.x; f < 64 * 16; f += 128) {
            int r = f >> 4;
            int c = f & 15;
            ((float4*)Ks[r])[c] = ((const float4*)(Kbase + (size_t)(base + r) * EMB))[c];
            ((float4*)Vs[r])[c] = ((const float4*)(Vbase + (size_t)(base + r) * EMB))[c];
        }
        __syncthreads();

#pragma unroll 1
        for (int sc = 0; sc < 4; sc++) {
            const int j0 = base + sc * 16;
            if (j0 > qi) break;

            float s[16];
#pragma unroll
            for (int j = 0; j < 16; j++) {
                const float4* kr = (const float4*)Ks[sc * 16 + j];
                float acc0 = 0.f, acc1 = 0.f, acc2 = 0.f, acc3 = 0.f;
#pragma unroll
                for (int d = 0; d < 16; d += 4) {
                    float4 k0v = kr[d + 0];
                    float4 k1v = kr[d + 1];
                    float4 k2v = kr[d + 2];
                    float4 k3v = kr[d + 3];
                    acc0 += q4[d+0].x*k0v.x + q4[d+0].y*k0v.y + q4[d+0].z*k0v.z + q4[d+0].w*k0v.w;
                    acc1 += q4[d+1].x*k1v.x + q4[d+1].y*k1v.y + q4[d+1].z*k1v.z + q4[d+1].w*k1v.w;
                    acc2 += q4[d+2].x*k2v.x + q4[d+2].y*k2v.y + q4[d+2].z*k2v.z + q4[d+2].w*k2v.w;
                    acc3 += q4[d+3].x*k3v.x + q4[d+3].y*k3v.y + q4[d+3].z*k3v.z + q4[d+3].w*k3v.w;
                }
                float sv = (acc0 + acc1 + acc2 + acc3) * ATTN_SCALE;
                s[j] = (j0 + j > qi) ? -1e30f : sv;
            }

            float cmax = s[0];
#pragma unroll
            for (int j = 1; j < 16; j++) cmax = fmaxf(cmax, s[j]);
            float mn   = fmaxf(m, cmax);
            float corr = __expf(m - mn);
            l *= corr;
#pragma unroll
            for (int i = 0; i < 16; i++) {
                o4[i].x *= corr; o4[i].y *= corr; o4[i].z *= corr; o4[i].w *= corr;
            }
            m = mn;

#pragma unroll
            for (int j = 0; j < 16; j++) {
                float p = __expf(s[j] - mn);
                l += p;
                const float4* vr = (const float4*)Vs[sc * 16 + j];
#pragma unroll
                for (int d = 0; d < 16; d++) {
                    float4 vv = vr[d];
                    o4[d].x += p * vv.x;
                    o4[d].y += p * vv.y;
                    o4[d].z += p * vv.z;
                    o4[d].w += p * vv.w;
                }
            }
        }
    }

    const float inv = 1.f / l;
    float* optr = O + ((size_t)(b * SEQ + qi)) * EMB + h * HDIM;
#pragma unroll
    for (int i = 0; i < 16; i++) {
        float4 st;
        st.x = o4[i].x * inv; st.y = o4[i].y * inv;
        st.z = o4[i].z * inv; st.w = o4[i].w * inv;
        ((float4*)optr)[i] = st;
    }
}

// ---------------------------------------------------------------------------
// Launch
// ---------------------------------------------------------------------------
extern "C" void kernel_launch(void* const* d_in, const int* in_sizes, int n_in,
                              void* d_out, int out_size)
{
    const float* xq = (const float*)d_in[0];
    const float* xk = (const float*)d_in[1];
    const float* xv = (const float*)d_in[2];
    // d_in[3] = mask (deterministic causal tril) — exploited structurally
    const float* Wq = (const float*)d_in[4];
    const float* bq = (const float*)d_in[5];
    const float* Wk = (const float*)d_in[6];
    const float* bk = (const float*)d_in[7];
    const float* Wv = (const float*)d_in[8];
    const float* bv = (const float*)d_in[9];
    const float* Wo = (const float*)d_in[10];
    const float* bo = (const float*)d_in[11];
    float* out = (float*)d_out;

    float *pQ, *pK, *pV, *pA;
    cudaGetSymbolAddress((void**)&pQ, g_Q);
    cudaGetSymbolAddress((void**)&pK, g_K);
    cudaGetSymbolAddress((void**)&pV, g_V);
    cudaGetSymbolAddress((void**)&pA, g_A);

    dim3 ggrid(EMB / 128, MROWS / 128);   // (8, 32)
    gemm_tf32<<<ggrid, 256>>>(xq, Wq, bq, pQ);
    gemm_tf32<<<ggrid, 256>>>(xk, Wk, bk, pK);
    gemm_tf32<<<ggrid, 256>>>(xv, Wv, bv, pV);

    dim3 agrid(SEQ / 128, BATCH * NHEAD); // (16, 32)
    attn_kernel<<<agrid, 128>>>(pQ, pK, pV, pA);

    gemm_tf32<<<ggrid, 256>>>(pA, Wo, bo, out);
}

// round 4
// speedup vs baseline: 1.4946x; 1.1191x over previous
#include <cuda_runtime.h>
#include <cuda_bf16.h>
#include <stdint.h>
#include <math.h>

// Problem constants
#define BATCH 2
#define SEQ   2048
#define EMB   1024
#define NHEAD 16
#define HDIM  64
#define MROWS (BATCH * SEQ)      // 4096
#define ATTN_SCALE 0.125f        // 1/sqrt(64)
#define NKS (EMB / 32)           // 32 k-steps

// ---------------------------------------------------------------------------
// Scratch (allocation-free rule: __device__ globals)
// ---------------------------------------------------------------------------
__device__ float g_Q[MROWS * EMB];
__device__ float g_K[MROWS * EMB];
__device__ float g_V[MROWS * EMB];
__device__ float g_A[MROWS * EMB];
__device__ float g_RX[MROWS * EMB];   // tf32-rounded activation input
__device__ float g_RW[EMB * EMB];     // tf32-rounded weight

// ---------------------------------------------------------------------------
// helpers
// ---------------------------------------------------------------------------
__device__ __forceinline__ uint32_t f2tf32(float x) {
    uint32_t u;
    asm("cvt.rna.tf32.f32 %0, %1;" : "=r"(u) : "f"(x));
    return u;
}
__device__ __forceinline__ float tf32r(float x) { return __uint_as_float(f2tf32(x)); }

__device__ __forceinline__ void mma8(float* c, const uint32_t* a, const uint32_t* b) {
    asm volatile(
        "mma.sync.aligned.m16n8k8.row.col.f32.tf32.tf32.f32 "
        "{%0,%1,%2,%3}, {%4,%5,%6,%7}, {%8,%9}, {%0,%1,%2,%3};"
        : "+f"(c[0]), "+f"(c[1]), "+f"(c[2]), "+f"(c[3])
        : "r"(a[0]), "r"(a[1]), "r"(a[2]), "r"(a[3]), "r"(b[0]), "r"(b[1]));
}

__device__ __forceinline__ void cpa16(uint32_t s, const void* g) {
    asm volatile("cp.async.cg.shared.global [%0], [%1], 16;\n" :: "r"(s), "l"(g));
}
#define CP_COMMIT() asm volatile("cp.async.commit_group;\n" ::: "memory")
#define CP_WAIT2()  asm volatile("cp.async.wait_group 2;\n"  ::: "memory")

__device__ __forceinline__ void ldsm4(uint32_t& r0, uint32_t& r1, uint32_t& r2,
                                      uint32_t& r3, uint32_t addr) {
    asm volatile("ldmatrix.sync.aligned.m8n8.x4.shared.b16 {%0,%1,%2,%3}, [%4];"
                 : "=r"(r0), "=r"(r1), "=r"(r2), "=r"(r3) : "r"(addr));
}

// ---------------------------------------------------------------------------
// tf32 rounding pre-pass (elementwise, vectorized)
// ---------------------------------------------------------------------------
__global__ void __launch_bounds__(256)
round_tf32_kernel(const float4* __restrict__ in, float4* __restrict__ out)
{
    int i = blockIdx.x * 256 + threadIdx.x;
    float4 v = in[i];
    v.x = tf32r(v.x); v.y = tf32r(v.y); v.z = tf32r(v.z); v.w = tf32r(v.w);
    out[i] = v;
}

// ---------------------------------------------------------------------------
// GEMM v3: C[4096,1024] = A @ W^T + bias. Inputs pre-rounded to tf32.
// CTA 128x128, k-step 32. 3-stage cp.async pipeline, SW128 swizzled SMEM,
// ldmatrix fragment loads, mma.m16n8k8.tf32.
// Tile in SMEM: 128 rows x 128 bytes; 16B chunk c of row r stored at
//   r*128 + ((c ^ (r&7)) * 16).
// ---------------------------------------------------------------------------
#define STAGE_BYTES 32768          // A tile 16KB + B tile 16KB
#define GEMM_SMEM   (3 * STAGE_BYTES)

__global__ void __launch_bounds__(256)
gemm_tf32_v3(const float* __restrict__ A, const float* __restrict__ Bw,
             const float* __restrict__ bias, float* __restrict__ C)
{
    extern __shared__ __align__(128) char dynsmem[];
    const uint32_t smemBase = (uint32_t)__cvta_generic_to_shared(dynsmem);

    const int tid  = threadIdx.x;
    const int lane = tid & 31;
    const int warp = tid >> 5;
    const int wm   = warp & 1;     // m offset wm*64
    const int wn   = warp >> 1;    // n offset wn*32
    const int rowBlk = blockIdx.y * 128;
    const int colBlk = blockIdx.x * 128;

    // per-thread cp.async chunk coords (4 chunks per tile per thread)
    int crow[4], csw[4];
#pragma unroll
    for (int i = 0; i < 4; i++) {
        int cid = tid + i * 256;        // 0..1023
        int r   = cid >> 3;
        int cc  = cid & 7;
        crow[i] = r;
        csw[i]  = r * 128 + ((cc ^ (r & 7)) << 4);
    }

    float acc[4][4][4];
#pragma unroll
    for (int mi = 0; mi < 4; mi++)
#pragma unroll
        for (int ni = 0; ni < 4; ni++)
#pragma unroll
            for (int q = 0; q < 4; q++) acc[mi][ni][q] = 0.f;

    // ldmatrix lane-address components (k-independent parts)
    // A: row = wm*64 + mt*16 + (lane&15); chunk = 2kt + (lane>>4)
    // B: row = wn*32 + p*16 + ((lane>>4)<<3) + (lane&7); chunk = 2kt + ((lane>>3)&1)
    const int aRowL = (lane & 15);
    const int aChL  = (lane >> 4);
    const int bRowL = ((lane >> 4) << 3) + (lane & 7);
    const int bChL  = ((lane >> 3) & 1);

    auto issue = [&](int ks, int stage) {
        uint32_t sA = smemBase + stage * STAGE_BYTES;
        uint32_t sB = sA + 16384;
        const float* Ag = A  + (size_t)rowBlk * EMB + ks * 32;
        const float* Bg = Bw + (size_t)colBlk * EMB + ks * 32;
#pragma unroll
        for (int i = 0; i < 4; i++) {
            int cid = tid + i * 256;
            int cc  = cid & 7;
            cpa16(sA + csw[i], Ag + (size_t)crow[i] * EMB + cc * 4);
            cpa16(sB + csw[i], Bg + (size_t)crow[i] * EMB + cc * 4);
        }
    };

    issue(0, 0); CP_COMMIT();
    issue(1, 1); CP_COMMIT();

#pragma unroll 1
    for (int ks = 0; ks < NKS; ks++) {
        if (ks + 2 < NKS) issue(ks + 2, (ks + 2) % 3);
        CP_COMMIT();
        CP_WAIT2();
        __syncthreads();

        uint32_t sA = smemBase + (ks % 3) * STAGE_BYTES;
        uint32_t sB = sA + 16384;

#pragma unroll
        for (int kt = 0; kt < 4; kt++) {
            uint32_t af[4][4];
            uint32_t bf[4][2];
#pragma unroll
            for (int mt = 0; mt < 4; mt++) {
                int r  = wm * 64 + mt * 16 + aRowL;
                int ch = 2 * kt + aChL;
                uint32_t addr = sA + r * 128 + ((ch ^ (r & 7)) << 4);
                ldsm4(af[mt][0], af[mt][1], af[mt][2], af[mt][3], addr);
            }
#pragma unroll
            for (int p = 0; p < 2; p++) {
                int r  = wn * 32 + p * 16 + bRowL;
                int ch = 2 * kt + bChL;
                uint32_t addr = sB + r * 128 + ((ch ^ (r & 7)) << 4);
                uint32_t t0, t1, t2, t3;
                ldsm4(t0, t1, t2, t3, addr);
                bf[2 * p][0] = t0; bf[2 * p][1] = t1;
                bf[2 * p + 1][0] = t2; bf[2 * p + 1][1] = t3;
            }
#pragma unroll
            for (int mi = 0; mi < 4; mi++)
#pragma unroll
                for (int ni = 0; ni < 4; ni++)
                    mma8(acc[mi][ni], af[mi], bf[ni]);
        }
        __syncthreads();
    }

    // ---- epilogue: bias + store ----
    const int g  = lane >> 2;
    const int tg = lane & 3;
#pragma unroll
    for (int mi = 0; mi < 4; mi++) {
        int r0 = rowBlk + wm * 64 + mi * 16 + g;
#pragma unroll
        for (int ni = 0; ni < 4; ni++) {
            int c0 = colBlk + wn * 32 + ni * 8 + tg * 2;
            float2 bb = *(const float2*)&bias[c0];
            float2 s0 = make_float2(acc[mi][ni][0] + bb.x, acc[mi][ni][1] + bb.y);
            float2 s1 = make_float2(acc[mi][ni][2] + bb.x, acc[mi][ni][3] + bb.y);
            *(float2*)&C[(size_t)r0 * EMB + c0]       = s0;
            *(float2*)&C[(size_t)(r0 + 8) * EMB + c0] = s1;
        }
    }
}

// ---------------------------------------------------------------------------
// Causal flash attention (fp32, 1 query/thread). Output stored tf32-rounded
// so the final projection GEMM can consume it directly.
// ---------------------------------------------------------------------------
__global__ void __launch_bounds__(128)
attn_kernel(const float* __restrict__ Q, const float* __restrict__ K,
            const float* __restrict__ V, float* __restrict__ O)
{
    __shared__ float Ks[64][64];
    __shared__ float Vs[64][64];

    const int bh = blockIdx.y;
    const int b  = bh >> 4;
    const int h  = bh & 15;
    const int qi = blockIdx.x * 128 + threadIdx.x;

    const float* qptr = Q + ((size_t)(b * SEQ + qi)) * EMB + h * HDIM;
    float4 q4[16];
#pragma unroll
    for (int i = 0; i < 16; i++) q4[i] = ((const float4*)qptr)[i];

    float4 o4[16];
#pragma unroll
    for (int i = 0; i < 16; i++) o4[i] = make_float4(0.f, 0.f, 0.f, 0.f);

    float m = -1e30f, l = 0.f;

    const float* Kbase = K + ((size_t)b * SEQ) * EMB + h * HDIM;
    const float* Vbase = V + ((size_t)b * SEQ) * EMB + h * HDIM;

    const int nTiles = blockIdx.x * 2 + 2;

    for (int t = 0; t < nTiles; t++) {
        const int base = t * 64;
        __syncthreads();
        for (int f = threadIdx.x; f < 64 * 16; f += 128) {
            int r = f >> 4;
            int c = f & 15;
            ((float4*)Ks[r])[c] = ((const float4*)(Kbase + (size_t)(base + r) * EMB))[c];
            ((float4*)Vs[r])[c] = ((const float4*)(Vbase + (size_t)(base + r) * EMB))[c];
        }
        __syncthreads();

#pragma unroll 1
        for (int sc = 0; sc < 4; sc++) {
            const int j0 = base + sc * 16;
            if (j0 > qi) break;

            float s[16];
#pragma unroll
            for (int j = 0; j < 16; j++) {
                const float4* kr = (const float4*)Ks[sc * 16 + j];
                float acc0 = 0.f, acc1 = 0.f, acc2 = 0.f, acc3 = 0.f;
#pragma unroll
                for (int d = 0; d < 16; d += 4) {
                    float4 k0v = kr[d + 0];
                    float4 k1v = kr[d + 1];
                    float4 k2v = kr[d + 2];
                    float4 k3v = kr[d + 3];
                    acc0 += q4[d+0].x*k0v.x + q4[d+0].y*k0v.y + q4[d+0].z*k0v.z + q4[d+0].w*k0v.w;
                    acc1 += q4[d+1].x*k1v.x + q4[d+1].y*k1v.y + q4[d+1].z*k1v.z + q4[d+1].w*k1v.w;
                    acc2 += q4[d+2].x*k2v.x + q4[d+2].y*k2v.y + q4[d+2].z*k2v.z + q4[d+2].w*k2v.w;
                    acc3 += q4[d+3].x*k3v.x + q4[d+3].y*k3v.y + q4[d+3].z*k3v.z + q4[d+3].w*k3v.w;
                }
                float sv = (acc0 + acc1 + acc2 + acc3) * ATTN_SCALE;
                s[j] = (j0 + j > qi) ? -1e30f : sv;
            }

            float cmax = s[0];
#pragma unroll
            for (int j = 1; j < 16; j++) cmax = fmaxf(cmax, s[j]);
            float mn   = fmaxf(m, cmax);
            float corr = __expf(m - mn);
            l *= corr;
#pragma unroll
            for (int i = 0; i < 16; i++) {
                o4[i].x *= corr; o4[i].y *= corr; o4[i].z *= corr; o4[i].w *= corr;
            }
            m = mn;

#pragma unroll
            for (int j = 0; j < 16; j++) {
                float p = __expf(s[j] - mn);
                l += p;
                const float4* vr = (const float4*)Vs[sc * 16 + j];
#pragma unroll
                for (int d = 0; d < 16; d++) {
                    float4 vv = vr[d];
                    o4[d].x += p * vv.x;
                    o4[d].y += p * vv.y;
                    o4[d].z += p * vv.z;
                    o4[d].w += p * vv.w;
                }
            }
        }
    }

    const float inv = 1.f / l;
    float* optr = O + ((size_t)(b * SEQ + qi)) * EMB + h * HDIM;
#pragma unroll
    for (int i = 0; i < 16; i++) {
        float4 st;
        st.x = tf32r(o4[i].x * inv); st.y = tf32r(o4[i].y * inv);
        st.z = tf32r(o4[i].z * inv); st.w = tf32r(o4[i].w * inv);
        ((float4*)optr)[i] = st;
    }
}

// ---------------------------------------------------------------------------
// Launch
// ---------------------------------------------------------------------------
extern "C" void kernel_launch(void* const* d_in, const int* in_sizes, int n_in,
                              void* d_out, int out_size)
{
    const float* xq = (const float*)d_in[0];
    const float* xk = (const float*)d_in[1];
    const float* xv = (const float*)d_in[2];
    // d_in[3] = mask (deterministic causal tril) — exploited structurally
    const float* Wq = (const float*)d_in[4];
    const float* bq = (const float*)d_in[5];
    const float* Wk = (const float*)d_in[6];
    const float* bk = (const float*)d_in[7];
    const float* Wv = (const float*)d_in[8];
    const float* bv = (const float*)d_in[9];
    const float* Wo = (const float*)d_in[10];
    const float* bo = (const float*)d_in[11];
    float* out = (float*)d_out;

    float *pQ, *pK, *pV, *pA, *pRX, *pRW;
    cudaGetSymbolAddress((void**)&pQ,  g_Q);
    cudaGetSymbolAddress((void**)&pK,  g_K);
    cudaGetSymbolAddress((void**)&pV,  g_V);
    cudaGetSymbolAddress((void**)&pA,  g_A);
    cudaGetSymbolAddress((void**)&pRX, g_RX);
    cudaGetSymbolAddress((void**)&pRW, g_RW);

    cudaFuncSetAttribute(gemm_tf32_v3,
                         cudaFuncAttributeMaxDynamicSharedMemorySize, GEMM_SMEM);

    dim3 ggrid(EMB / 128, MROWS / 128);   // (8, 32)
    const int rX = (MROWS * EMB / 4) / 256;   // blocks for activation rounding
    const int rW = (EMB * EMB / 4) / 256;     // blocks for weight rounding

    // Q projection
    round_tf32_kernel<<<rX, 256>>>((const float4*)xq, (float4*)pRX);
    round_tf32_kernel<<<rW, 256>>>((const float4*)Wq, (float4*)pRW);
    gemm_tf32_v3<<<ggrid, 256, GEMM_SMEM>>>(pRX, pRW, bq, pQ);
    // K projection
    round_tf32_kernel<<<rX, 256>>>((const float4*)xk, (float4*)pRX);
    round_tf32_kernel<<<rW, 256>>>((const float4*)Wk, (float4*)pRW);
    gemm_tf32_v3<<<ggrid, 256, GEMM_SMEM>>>(pRX, pRW, bk, pK);
    // V projection
    round_tf32_kernel<<<rX, 256>>>((const float4*)xv, (float4*)pRX);
    round_tf32_kernel<<<rW, 256>>>((const float4*)Wv, (float4*)pRW);
    gemm_tf32_v3<<<ggrid, 256, GEMM_SMEM>>>(pRX, pRW, bv, pV);

    // attention (writes tf32-rounded output)
    dim3 agrid(SEQ / 128, BATCH * NHEAD); // (16, 32)
    attn_kernel<<<agrid, 128>>>(pQ, pK, pV, pA);

    // O projection
    round_tf32_kernel<<<rW, 256>>>((const float4*)Wo, (float4*)pRW);
    gemm_tf32_v3<<<ggrid, 256, GEMM_SMEM>>>(pA, pRW, bo, out);
}